// round 4
// baseline (speedup 1.0000x reference)
#include <cuda_runtime.h>
#include <cstdint>

// ============================================================
// WeightOnlyInt8Linear: out = input @ weight^T * scales
// R4: int8 IMMA path (mma.m16n8k32.s8 = 4096 MAC/instr vs tf32's 1024).
// Activation split into two int8 digits per row:
//   a = s_hi*a_hi + s_lo*a_lo,  s_hi = rowmax/127, s_lo = s_hi/252
//   quant error <= s_hi/504  ->  output rel err ~4e-5
// Dual int32 accumulators, one fused kernel.
// Pre-passes store A/W in FRAGMENT-MAJOR layout so every smem fragment
// load is a conflict-free sequential LDS.64 (addr = base + lane*8).
// CTA 128x128x(k)128, 256 thr, warp tile 64x32, 3-stage cp.async.
// ============================================================

static constexpr int MDIM = 8192;
static constexpr int NDIM = 4096;
static constexpr int KDIM = 4096;

static constexpr int BM = 128;
static constexpr int BN = 128;
static constexpr int BK = 128;            // 4 k-steps of 32
static constexpr int STAGES = 3;
static constexpr int NKT = KDIM / BK;     // 32

static constexpr int A_ST_BYTES = (BM / 16) * (BK / 32) * 512;  // 16384
static constexpr int B_ST_BYTES = (BN / 8) * (BK / 32) * 256;   // 16384
static constexpr int STAGE_BYTES = 2 * A_ST_BYTES + B_ST_BYTES; // 49152 (Ahi,Alo,B)
static constexpr int SMEM_BYTES = STAGES * STAGE_BYTES;          // 147456

// static device scratch (allocation-free)
__device__ int8_t g_ah[(size_t)MDIM * KDIM];   // 32 MB, fragment-major
__device__ int8_t g_al[(size_t)MDIM * KDIM];   // 32 MB
__device__ int8_t g_wq[(size_t)NDIM * KDIM];   // 16 MB, fragment-major
__device__ float  g_sh[MDIM];
__device__ float  g_sl[MDIM];

// ---------------- helpers ----------------
__device__ __forceinline__ uint32_t smem_u32(const void* p) {
    uint32_t a;
    asm("{ .reg .u64 t; cvta.to.shared.u64 t, %1; cvt.u32.u64 %0, t; }"
        : "=r"(a) : "l"(p));
    return a;
}

__device__ __forceinline__ void cp_async16(uint32_t dst, const void* src) {
    asm volatile("cp.async.cg.shared.global [%0], [%1], 16;"
                 :: "r"(dst), "l"(src) : "memory");
}
#define CP_COMMIT() asm volatile("cp.async.commit_group;" ::: "memory")
#define CP_WAIT(n)  asm volatile("cp.async.wait_group %0;" :: "n"(n) : "memory")

// d += a*b  (m16n8k32 s8 -> s32)
#define MMA_S8(d, a0, a1, a2, a3, b0, b1)                                     \
    asm volatile("mma.sync.aligned.m16n8k32.row.col.s32.s8.s8.s32 "           \
                 "{%0,%1,%2,%3}, {%4,%5,%6,%7}, {%8,%9}, {%0,%1,%2,%3};"      \
                 : "+r"((d)[0]), "+r"((d)[1]), "+r"((d)[2]), "+r"((d)[3])     \
                 : "r"(a0), "r"(a1), "r"(a2), "r"(a3), "r"(b0), "r"(b1))

// fragment byte map within one 32-k block for thread-in-group tt, byte j:
//   j<4 -> k = 4*tt + j ; j>=4 -> k = 16 + 4*tt + (j-4)
__device__ __forceinline__ int frag_k(int tt, int j) {
    return (j < 4) ? (4 * tt + j) : (16 + 4 * tt + (j - 4));
}

// ---------------- activation quantize + split + pack ----------------
// one block (128 thr) per row; thread t handles k-block ks = t (32 floats)
__global__ void __launch_bounds__(128) quant_a_kernel(const float* __restrict__ a) {
    const int row = blockIdx.x;
    const int t   = threadIdx.x;
    const float* ar = a + (size_t)row * KDIM + t * 32;

    float v[32];
    #pragma unroll
    for (int i = 0; i < 8; i++) {
        float4 q = reinterpret_cast<const float4*>(ar)[i];
        v[i * 4 + 0] = q.x; v[i * 4 + 1] = q.y;
        v[i * 4 + 2] = q.z; v[i * 4 + 3] = q.w;
    }
    float mx = 0.0f;
    #pragma unroll
    for (int i = 0; i < 32; i++) mx = fmaxf(mx, fabsf(v[i]));

    __shared__ float red[128];
    red[t] = mx;
    __syncthreads();
    #pragma unroll
    for (int o = 64; o > 0; o >>= 1) {
        if (t < o) red[t] = fmaxf(red[t], red[t + o]);
        __syncthreads();
    }
    const float rowmax = fmaxf(red[0], 1e-30f);
    const float s_hi   = rowmax / 127.0f;
    const float inv_hi = 127.0f / rowmax;
    const float s_lo   = s_hi / 252.0f;
    const float inv_lo = 252.0f / s_hi;
    if (t == 0) { g_sh[row] = s_hi; g_sl[row] = s_lo; }

    int hb[32], lb[32];
    #pragma unroll
    for (int i = 0; i < 32; i++) {
        float q = rintf(v[i] * inv_hi);
        q = fminf(fmaxf(q, -127.0f), 127.0f);
        float r = v[i] - q * s_hi;
        float ql = rintf(r * inv_lo);
        ql = fminf(fmaxf(ql, -127.0f), 127.0f);
        hb[i] = (int)q;
        lb[i] = (int)ql;
    }

    // pack into fragment-major 32B: out[tt*8+j] = digit[frag_k(tt,j)]
    uint32_t hw[8] = {0,0,0,0,0,0,0,0}, lw[8] = {0,0,0,0,0,0,0,0};
    #pragma unroll
    for (int tt = 0; tt < 4; tt++)
        #pragma unroll
        for (int j = 0; j < 8; j++) {
            int ob = tt * 8 + j;
            int k  = frag_k(tt, j);
            hw[ob >> 2] |= (uint32_t)(hb[k] & 0xff) << ((ob & 3) * 8);
            lw[ob >> 2] |= (uint32_t)(lb[k] & 0xff) << ((ob & 3) * 8);
        }

    const int rt = row >> 4, h = (row >> 3) & 1, g = row & 7;
    const size_t base = (((size_t)(rt * 128 + t) * 2 + h) << 8) + g * 32;  // *256
    int4* dh = reinterpret_cast<int4*>(g_ah + base);
    int4* dl = reinterpret_cast<int4*>(g_al + base);
    dh[0] = make_int4(hw[0], hw[1], hw[2], hw[3]);
    dh[1] = make_int4(hw[4], hw[5], hw[6], hw[7]);
    dl[0] = make_int4(lw[0], lw[1], lw[2], lw[3]);
    dl[1] = make_int4(lw[4], lw[5], lw[6], lw[7]);
}

// ---------------- weight pack: int32 -> int8, fragment-major ----------------
// one block (128 thr) per output col; thread t handles k-block ks = t
__global__ void __launch_bounds__(128) pack_w_kernel(const int* __restrict__ w) {
    const int col = blockIdx.x;
    const int t   = threadIdx.x;
    const int* wr = w + (size_t)col * KDIM + t * 32;

    int wv[32];
    #pragma unroll
    for (int i = 0; i < 8; i++) {
        int4 q = reinterpret_cast<const int4*>(wr)[i];
        wv[i * 4 + 0] = q.x; wv[i * 4 + 1] = q.y;
        wv[i * 4 + 2] = q.z; wv[i * 4 + 3] = q.w;
    }
    uint32_t pw[8] = {0,0,0,0,0,0,0,0};
    #pragma unroll
    for (int tt = 0; tt < 4; tt++)
        #pragma unroll
        for (int j = 0; j < 8; j++) {
            int ob = tt * 8 + j;
            int k  = frag_k(tt, j);
            pw[ob >> 2] |= (uint32_t)(wv[k] & 0xff) << ((ob & 3) * 8);
        }
    const int nt = col >> 3, g = col & 7;
    const size_t base = (((size_t)(nt * 128 + t)) << 8) + g * 32;  // *256
    int4* d = reinterpret_cast<int4*>(g_wq + base);
    d[0] = make_int4(pw[0], pw[1], pw[2], pw[3]);
    d[1] = make_int4(pw[4], pw[5], pw[6], pw[7]);
}

// ---------------- main GEMM ----------------
__global__ void __launch_bounds__(256, 1) gemm_kernel(
    const float* __restrict__ scales, float* __restrict__ out)
{
    extern __shared__ int8_t smem[];
    const uint32_t sbase = smem_u32(smem);

    const int tid  = threadIdx.x;
    const int lane = tid & 31;
    const int wid  = tid >> 5;        // 0..7
    const int wm   = wid >> 2;        // 0..1  (64-row slab)
    const int wn   = wid & 3;         // 0..3  (32-col slab)
    const int g    = lane >> 2;
    const int t    = lane & 3;

    // grouped-M raster (8 m-tiles per group over 32 n-tiles)
    const int num_n  = NDIM / BN;     // 32
    const int GROUPM = 8;
    const int bid = blockIdx.x;
    const int grp = bid / (GROUPM * num_n);
    const int rem = bid % (GROUPM * num_n);
    const int mtile = grp * GROUPM + (rem % GROUPM);
    const int ntile = rem / GROUPM;
    const int m0 = mtile * BM;
    const int n0 = ntile * BN;
    const int rt0 = m0 >> 4;          // global 16-row tile index
    const int nt0 = n0 >> 3;          // global 8-col tile index

    int acch[4][4][4], accl[4][4][4];
    #pragma unroll
    for (int i = 0; i < 4; i++)
        #pragma unroll
        for (int j = 0; j < 4; j++)
            #pragma unroll
            for (int c = 0; c < 4; c++) { acch[i][j][c] = 0; accl[i][j][c] = 0; }

    #define ISSUE_STAGE(kt_, slot_)                                             \
    do {                                                                        \
        const int _ks0 = (kt_) * 4;                                             \
        const uint32_t _sa  = sbase + (uint32_t)(slot_) * STAGE_BYTES;          \
        const uint32_t _sal = _sa + A_ST_BYTES;                                 \
        const uint32_t _sb  = _sa + 2 * A_ST_BYTES;                             \
        _Pragma("unroll")                                                       \
        for (int u = tid; u < 1024; u += 256) {                                 \
            const int mtb = u >> 5;      /* mt*4+b */                           \
            const int off = (u & 31) << 4;                                      \
            const size_t gi =                                                   \
                (((size_t)((rt0 + (mtb >> 2)) * 128 + _ks0 + (mtb & 3))) << 9)  \
                + off;                                                          \
            cp_async16(_sa  + (u << 4), g_ah + gi);                             \
            cp_async16(_sal + (u << 4), g_al + gi);                             \
        }                                                                       \
        _Pragma("unroll")                                                       \
        for (int u = tid; u < 1024; u += 256) {                                 \
            const int ntb = u >> 4;      /* nt*4+b */                           \
            const int off = (u & 15) << 4;                                      \
            const size_t gi =                                                   \
                (((size_t)((nt0 + (ntb >> 2)) * 128 + _ks0 + (ntb & 3))) << 8)  \
                + off;                                                          \
            cp_async16(_sb + (u << 4), g_wq + gi);                              \
        }                                                                       \
    } while (0)

    ISSUE_STAGE(0, 0); CP_COMMIT();
    ISSUE_STAGE(1, 1); CP_COMMIT();

    int s_cur = 0, s_nxt = 2;
    const uint32_t lane8 = (uint32_t)lane * 8;

    for (int kt = 0; kt < NKT; kt++) {
        CP_WAIT(1);
        __syncthreads();

        const int kn = kt + 2;
        if (kn < NKT) { ISSUE_STAGE(kn, s_nxt); }
        CP_COMMIT();

        const uint32_t sa  = sbase + (uint32_t)s_cur * STAGE_BYTES;
        const uint32_t sal = sa + A_ST_BYTES;
        const uint32_t sb  = sa + 2 * A_ST_BYTES;

        #pragma unroll
        for (int b = 0; b < 4; b++) {
            uint32_t bf[4][2];
            #pragma unroll
            for (int j = 0; j < 4; j++) {
                uint32_t addr = sb + (uint32_t)(((wn * 4 + j) * 4 + b) * 256) + lane8;
                asm volatile("ld.shared.v2.u32 {%0,%1}, [%2];"
                             : "=r"(bf[j][0]), "=r"(bf[j][1]) : "r"(addr));
            }
            #pragma unroll
            for (int i = 0; i < 4; i++) {
                const uint32_t abase = (uint32_t)(((wm * 4 + i) * 4 + b) * 512) + lane8;
                uint32_t a0, a1, a2, a3;
                asm volatile("ld.shared.v2.u32 {%0,%1}, [%2];"
                             : "=r"(a0), "=r"(a2) : "r"(sa + abase));
                asm volatile("ld.shared.v2.u32 {%0,%1}, [%2];"
                             : "=r"(a1), "=r"(a3) : "r"(sa + abase + 256));
                #pragma unroll
                for (int j = 0; j < 4; j++)
                    MMA_S8(acch[i][j], a0, a1, a2, a3, bf[j][0], bf[j][1]);

                asm volatile("ld.shared.v2.u32 {%0,%1}, [%2];"
                             : "=r"(a0), "=r"(a2) : "r"(sal + abase));
                asm volatile("ld.shared.v2.u32 {%0,%1}, [%2];"
                             : "=r"(a1), "=r"(a3) : "r"(sal + abase + 256));
                #pragma unroll
                for (int j = 0; j < 4; j++)
                    MMA_S8(accl[i][j], a0, a1, a2, a3, bf[j][0], bf[j][1]);
            }
        }

        s_cur = (s_cur == 2) ? 0 : s_cur + 1;
        s_nxt = (s_nxt == 2) ? 0 : s_nxt + 1;
    }

    // ---- epilogue: out = (s_hi*acc_h + s_lo*acc_l) * scales[col] ----
    #pragma unroll
    for (int i = 0; i < 4; i++) {
        const int r0 = m0 + wm * 64 + i * 16 + g;
        const int r1 = r0 + 8;
        const float sh0 = g_sh[r0], sl0 = g_sl[r0];
        const float sh1 = g_sh[r1], sl1 = g_sl[r1];
        #pragma unroll
        for (int j = 0; j < 4; j++) {
            const int col = n0 + wn * 32 + j * 8 + 2 * t;
            const float2 sc = *reinterpret_cast<const float2*>(scales + col);
            float2 v0, v1;
            v0.x = (sh0 * (float)acch[i][j][0] + sl0 * (float)accl[i][j][0]) * sc.x;
            v0.y = (sh0 * (float)acch[i][j][1] + sl0 * (float)accl[i][j][1]) * sc.y;
            v1.x = (sh1 * (float)acch[i][j][2] + sl1 * (float)accl[i][j][2]) * sc.x;
            v1.y = (sh1 * (float)acch[i][j][3] + sl1 * (float)accl[i][j][3]) * sc.y;
            *reinterpret_cast<float2*>(out + (size_t)r0 * NDIM + col) = v0;
            *reinterpret_cast<float2*>(out + (size_t)r1 * NDIM + col) = v1;
        }
    }
}

// ---------------- host ----------------
extern "C" void kernel_launch(void* const* d_in, const int* in_sizes, int n_in,
                              void* d_out, int out_size) {
    const float* input  = (const float*)d_in[0];
    const int*   weight = (const int*)d_in[1];
    const float* scales = (const float*)d_in[2];
    float* out = (float*)d_out;

    quant_a_kernel<<<MDIM, 128>>>(input);
    pack_w_kernel<<<NDIM, 128>>>(weight);

    cudaFuncSetAttribute(gemm_kernel,
                         cudaFuncAttributeMaxDynamicSharedMemorySize, SMEM_BYTES);
    const int grid = (MDIM / BM) * (NDIM / BN);   // 2048
    gemm_kernel<<<grid, 256, SMEM_BYTES>>>(scales, out);
}

// round 5
// speedup vs baseline: 5.0794x; 5.0794x over previous
#include <cuda_runtime.h>
#include <cuda_fp16.h>
#include <cstdint>

// ============================================================
// WeightOnlyInt8Linear: out = input @ weight^T * scales
// R5: single-pass fp16 mma.m16n8k16 (2048 MAC/instr).
//   - weights |w|<=127 exact in fp16; activations fp16-rounded
//     (11-bit mantissa, same as tf32 -> rel_err ~4.2e-4).
//   - 67.1M mma instructions = half of R3's tf32 count.
// Fragment-major pre-pack: each A fragment = one LDS.128,
// each B fragment = one LDS.64, conflict-free.
// CTA 128x256x32, 256 thr, warp 64x64, 4-stage cp.async.
// ============================================================

static constexpr int MDIM = 8192;
static constexpr int NDIM = 4096;
static constexpr int KDIM = 4096;

static constexpr int BM = 128;
static constexpr int BN = 256;
static constexpr int BK = 32;             // 2 k16 steps
static constexpr int STAGES = 4;
static constexpr int NKT = KDIM / BK;     // 128

// per stage: A = (BM/16)*(BK/16)*512 = 8KB ; B = (BN/8)*(BK/16)*256 = 16KB
static constexpr int A_ST_BYTES = (BM / 16) * (BK / 16) * 512;   // 8192
static constexpr int B_ST_BYTES = (BN / 8) * (BK / 16) * 256;    // 16384
static constexpr int STAGE_BYTES = A_ST_BYTES + B_ST_BYTES;      // 24576
static constexpr int SMEM_BYTES = STAGES * STAGE_BYTES;          // 98304

// static scratch: fragment-major fp16
__device__ __half g_af[(size_t)MDIM * KDIM];   // 64 MB: [m16-tile][k16-tile][512B]
__device__ __half g_wf[(size_t)NDIM * KDIM];   // 32 MB: [n8-tile][k16-tile][256B]

// ---------------- helpers ----------------
__device__ __forceinline__ uint32_t smem_u32(const void* p) {
    uint32_t a;
    asm("{ .reg .u64 t; cvta.to.shared.u64 t, %1; cvt.u32.u64 %0, t; }"
        : "=r"(a) : "l"(p));
    return a;
}
__device__ __forceinline__ void cp_async16(uint32_t dst, const void* src) {
    asm volatile("cp.async.cg.shared.global [%0], [%1], 16;"
                 :: "r"(dst), "l"(src) : "memory");
}
#define CP_COMMIT() asm volatile("cp.async.commit_group;" ::: "memory")
#define CP_WAIT(n)  asm volatile("cp.async.wait_group %0;" :: "n"(n) : "memory")

// d += a*b (m16n8k16 f16 inputs, f32 accum)
#define MMA_F16(d, a0, a1, a2, a3, b0, b1)                                    \
    asm volatile("mma.sync.aligned.m16n8k16.row.col.f32.f16.f16.f32 "         \
                 "{%0,%1,%2,%3}, {%4,%5,%6,%7}, {%8,%9}, {%0,%1,%2,%3};"      \
                 : "+f"((d)[0]), "+f"((d)[1]), "+f"((d)[2]), "+f"((d)[3])     \
                 : "r"(a0), "r"(a1), "r"(a2), "r"(a3), "r"(b0), "r"(b1))

// ---------------- A pack: f32 -> f16 fragment-major ----------------
// block: 256 thr, tile = 16 rows x 512 k. grid = (KDIM/512, MDIM/16)
__global__ void __launch_bounds__(256) pack_a_kernel(const float* __restrict__ a) {
    const int rt = blockIdx.y;          // 16-row tile
    const int k0 = blockIdx.x * 512;
    __shared__ __half sh[16][520];      // row stride 1040B: conflict-free gather

    #pragma unroll
    for (int u = threadIdx.x; u < 2048; u += 256) {       // 16 rows * 128 float4
        const int row = u >> 7, c4 = u & 127;
        float4 v = *reinterpret_cast<const float4*>(
            a + (size_t)(rt * 16 + row) * KDIM + k0 + c4 * 4);
        __half2* d = reinterpret_cast<__half2*>(&sh[row][c4 * 4]);
        d[0] = __floats2half2_rn(v.x, v.y);
        d[1] = __floats2half2_rn(v.z, v.w);
    }
    __syncthreads();

    // emit fragments: 32 k16-tiles * 32 lanes, 16B each
    #pragma unroll
    for (int w = threadIdx.x; w < 1024; w += 256) {
        const int kt = w >> 5, lane = w & 31;
        const int g = lane >> 2, t = lane & 3;
        const int kc = kt * 16 + 2 * t;
        uint32_t r0 = *reinterpret_cast<const uint32_t*>(&sh[g][kc]);
        uint32_t r1 = *reinterpret_cast<const uint32_t*>(&sh[g + 8][kc]);
        uint32_t r2 = *reinterpret_cast<const uint32_t*>(&sh[g][kc + 8]);
        uint32_t r3 = *reinterpret_cast<const uint32_t*>(&sh[g + 8][kc + 8]);
        int4* dst = reinterpret_cast<int4*>(
            reinterpret_cast<char*>(g_af)
            + (((size_t)rt * 256 + (k0 >> 4) + kt) << 9) + lane * 16);
        *dst = make_int4(r0, r1, r2, r3);
    }
}

// ---------------- W pack: int32 -> f16 fragment-major ----------------
// block: 256 thr, tile = 8 cols x 512 k. grid = (KDIM/512, NDIM/8)
__global__ void __launch_bounds__(256) pack_w_kernel(const int* __restrict__ w) {
    const int nt = blockIdx.y;          // 8-col tile
    const int k0 = blockIdx.x * 512;
    __shared__ __half sh[8][520];

    #pragma unroll
    for (int u = threadIdx.x; u < 1024; u += 256) {       // 8 cols * 128 int4
        const int row = u >> 7, c4 = u & 127;
        int4 v = *reinterpret_cast<const int4*>(
            w + (size_t)(nt * 8 + row) * KDIM + k0 + c4 * 4);
        __half2* d = reinterpret_cast<__half2*>(&sh[row][c4 * 4]);
        d[0] = __floats2half2_rn((float)v.x, (float)v.y);
        d[1] = __floats2half2_rn((float)v.z, (float)v.w);
    }
    __syncthreads();

    #pragma unroll
    for (int u2 = threadIdx.x; u2 < 1024; u2 += 256) {    // 32 k16-tiles * 32 lanes, 8B
        const int kt = u2 >> 5, lane = u2 & 31;
        const int g = lane >> 2, t = lane & 3;
        const int kc = kt * 16 + 2 * t;
        uint32_t b0 = *reinterpret_cast<const uint32_t*>(&sh[g][kc]);
        uint32_t b1 = *reinterpret_cast<const uint32_t*>(&sh[g][kc + 8]);
        int2* dst = reinterpret_cast<int2*>(
            reinterpret_cast<char*>(g_wf)
            + (((size_t)nt * 256 + (k0 >> 4) + kt) << 8) + lane * 8);
        *dst = make_int2(b0, b1);
    }
}

// ---------------- main GEMM ----------------
__global__ void __launch_bounds__(256, 1) gemm_kernel(
    const float* __restrict__ scales, float* __restrict__ out)
{
    extern __shared__ char smem[];
    const uint32_t sbase = smem_u32(smem);

    const int tid  = threadIdx.x;
    const int lane = tid & 31;
    const int wid  = tid >> 5;        // 0..7
    const int wm   = wid >> 2;        // 0..1 (64-row slab)
    const int wn   = wid & 3;         // 0..3 (64-col slab)
    const int g    = lane >> 2;
    const int t    = lane & 3;

    // grouped-M raster
    const int num_n  = NDIM / BN;     // 16
    const int GROUPM = 8;
    const int bid = blockIdx.x;
    const int grp = bid / (GROUPM * num_n);
    const int rem = bid % (GROUPM * num_n);
    const int m0 = (grp * GROUPM + (rem % GROUPM)) * BM;
    const int n0 = (rem / GROUPM) * BN;
    const int rt0 = m0 >> 4;          // global m16-tile index
    const int nt0 = n0 >> 3;          // global n8-tile index

    float acc[4][8][4];
    #pragma unroll
    for (int i = 0; i < 4; i++)
        #pragma unroll
        for (int j = 0; j < 8; j++)
            #pragma unroll
            for (int c = 0; c < 4; c++) acc[i][j][c] = 0.0f;

    const char* gA = reinterpret_cast<const char*>(g_af);
    const char* gB = reinterpret_cast<const char*>(g_wf);

    #define ISSUE_STAGE(kt_)                                                   \
    do {                                                                       \
        const int _kt = (kt_);                                                 \
        const int _s  = _kt & (STAGES - 1);                                    \
        const uint32_t _sa = sbase + (uint32_t)_s * STAGE_BYTES;               \
        const uint32_t _sb = _sa + A_ST_BYTES;                                 \
        _Pragma("unroll")                                                      \
        for (int u = tid; u < 512; u += 256) {        /* A: 8KB */             \
            const int mi = u >> 6;                                             \
            cp_async16(_sa + (u << 4),                                         \
                gA + (((size_t)(rt0 + mi) * 256 + _kt * 2) << 9)               \
                   + ((u & 63) << 4));                                         \
        }                                                                      \
        _Pragma("unroll")                                                      \
        for (int u = tid; u < 1024; u += 256) {       /* B: 16KB */            \
            const int nj = u >> 5;                                             \
            cp_async16(_sb + (u << 4),                                         \
                gB + (((size_t)(nt0 + nj) * 256 + _kt * 2) << 8)               \
                   + ((u & 31) << 4));                                         \
        }                                                                      \
    } while (0)

    #pragma unroll
    for (int kt = 0; kt < STAGES - 1; kt++) { ISSUE_STAGE(kt); CP_COMMIT(); }

    const uint32_t lane16 = (uint32_t)lane * 16;
    const uint32_t lane8  = (uint32_t)lane * 8;

    for (int kt = 0; kt < NKT; kt++) {
        CP_WAIT(STAGES - 2);
        __syncthreads();

        const int kn = kt + STAGES - 1;
        if (kn < NKT) ISSUE_STAGE(kn);
        CP_COMMIT();

        const int s = kt & (STAGES - 1);
        const uint32_t sa = sbase + (uint32_t)s * STAGE_BYTES;
        const uint32_t sb = sa + A_ST_BYTES;

        #pragma unroll
        for (int ks = 0; ks < 2; ks++) {
            uint32_t bf[8][2];
            #pragma unroll
            for (int j = 0; j < 8; j++) {
                const uint32_t addr = sb + (uint32_t)((wn * 8 + j) * 512 + ks * 256) + lane8;
                asm volatile("ld.shared.v2.u32 {%0,%1}, [%2];"
                             : "=r"(bf[j][0]), "=r"(bf[j][1]) : "r"(addr));
            }
            #pragma unroll
            for (int i = 0; i < 4; i++) {
                uint32_t a0, a1, a2, a3;
                const uint32_t addr = sa + (uint32_t)((wm * 4 + i) * 1024 + ks * 512) + lane16;
                asm volatile("ld.shared.v4.u32 {%0,%1,%2,%3}, [%4];"
                             : "=r"(a0), "=r"(a1), "=r"(a2), "=r"(a3) : "r"(addr));
                #pragma unroll
                for (int j = 0; j < 8; j++)
                    MMA_F16(acc[i][j], a0, a1, a2, a3, bf[j][0], bf[j][1]);
            }
        }
    }

    // ---- epilogue: scale and store ----
    const int orow0 = m0 + wm * 64;
    const int ocol0 = n0 + wn * 64;
    #pragma unroll
    for (int j = 0; j < 8; j++) {
        const int col = ocol0 + j * 8 + 2 * t;
        const float2 sc = *reinterpret_cast<const float2*>(scales + col);
        #pragma unroll
        for (int i = 0; i < 4; i++) {
            const int row = orow0 + i * 16 + g;
            float2 v0 = { acc[i][j][0] * sc.x, acc[i][j][1] * sc.y };
            float2 v1 = { acc[i][j][2] * sc.x, acc[i][j][3] * sc.y };
            *reinterpret_cast<float2*>(out + (size_t)row * NDIM + col)       = v0;
            *reinterpret_cast<float2*>(out + (size_t)(row + 8) * NDIM + col) = v1;
        }
    }
}

// ---------------- host ----------------
extern "C" void kernel_launch(void* const* d_in, const int* in_sizes, int n_in,
                              void* d_out, int out_size) {
    const float* input  = (const float*)d_in[0];
    const int*   weight = (const int*)d_in[1];
    const float* scales = (const float*)d_in[2];
    float* out = (float*)d_out;

    {
        dim3 ga(KDIM / 512, MDIM / 16);   // (8, 512)
        pack_a_kernel<<<ga, 256>>>(input);
        dim3 gw(KDIM / 512, NDIM / 8);    // (8, 512)
        pack_w_kernel<<<gw, 256>>>(weight);
    }

    cudaFuncSetAttribute(gemm_kernel,
                         cudaFuncAttributeMaxDynamicSharedMemorySize, SMEM_BYTES);
    const int grid = (MDIM / BM) * (NDIM / BN);   // 1024
    gemm_kernel<<<grid, 256, SMEM_BYTES>>>(scales, out);
}

// round 6
// speedup vs baseline: 5.6398x; 1.1103x over previous
#include <cuda_runtime.h>
#include <cuda_fp16.h>
#include <cstdint>

// ============================================================
// WeightOnlyInt8Linear: out = input @ weight^T * scales
// R6: fp16 m16n8k16 GEMM, occupancy-2 config.
//   CTA 128x128x64, 3-stage cp.async (32KB/stage, 96KB smem),
//   256 thr, warp 64x32 (acc=64 regs, <=128 regs -> 2 CTA/SM).
//   2 resident CTAs hide per-ktile barrier + cp.async latency.
// Fragment-major pre-pack (one LDS.128 per A frag, LDS.64 per B).
// ============================================================

static constexpr int MDIM = 8192;
static constexpr int NDIM = 4096;
static constexpr int KDIM = 4096;

static constexpr int BM = 128;
static constexpr int BN = 128;
static constexpr int BK = 64;             // 4 k16 steps
static constexpr int STAGES = 3;
static constexpr int NKT = KDIM / BK;     // 64

static constexpr int A_ST_BYTES = (BM / 16) * (BK / 16) * 512;   // 16384
static constexpr int B_ST_BYTES = (BN / 8) * (BK / 16) * 256;    // 16384
static constexpr int STAGE_BYTES = A_ST_BYTES + B_ST_BYTES;      // 32768
static constexpr int SMEM_BYTES = STAGES * STAGE_BYTES;          // 98304... (3*32768=98304)

// static scratch: fragment-major fp16
__device__ __half g_af[(size_t)MDIM * KDIM];   // 64 MB: [m16-tile][k16-tile][512B]
__device__ __half g_wf[(size_t)NDIM * KDIM];   // 32 MB: [n8-tile][k16-tile][256B]

// ---------------- helpers ----------------
__device__ __forceinline__ uint32_t smem_u32(const void* p) {
    uint32_t a;
    asm("{ .reg .u64 t; cvta.to.shared.u64 t, %1; cvt.u32.u64 %0, t; }"
        : "=r"(a) : "l"(p));
    return a;
}
__device__ __forceinline__ void cp_async16(uint32_t dst, const void* src) {
    asm volatile("cp.async.cg.shared.global [%0], [%1], 16;"
                 :: "r"(dst), "l"(src) : "memory");
}
#define CP_COMMIT() asm volatile("cp.async.commit_group;" ::: "memory")
#define CP_WAIT(n)  asm volatile("cp.async.wait_group %0;" :: "n"(n) : "memory")

#define MMA_F16(d, a0, a1, a2, a3, b0, b1)                                    \
    asm volatile("mma.sync.aligned.m16n8k16.row.col.f32.f16.f16.f32 "         \
                 "{%0,%1,%2,%3}, {%4,%5,%6,%7}, {%8,%9}, {%0,%1,%2,%3};"      \
                 : "+f"((d)[0]), "+f"((d)[1]), "+f"((d)[2]), "+f"((d)[3])     \
                 : "r"(a0), "r"(a1), "r"(a2), "r"(a3), "r"(b0), "r"(b1))

// ---------------- A pack: f32 -> f16 fragment-major ----------------
__global__ void __launch_bounds__(256) pack_a_kernel(const float* __restrict__ a) {
    const int rt = blockIdx.y;
    const int k0 = blockIdx.x * 512;
    __shared__ __half sh[16][520];

    #pragma unroll
    for (int u = threadIdx.x; u < 2048; u += 256) {
        const int row = u >> 7, c4 = u & 127;
        float4 v = *reinterpret_cast<const float4*>(
            a + (size_t)(rt * 16 + row) * KDIM + k0 + c4 * 4);
        __half2* d = reinterpret_cast<__half2*>(&sh[row][c4 * 4]);
        d[0] = __floats2half2_rn(v.x, v.y);
        d[1] = __floats2half2_rn(v.z, v.w);
    }
    __syncthreads();

    #pragma unroll
    for (int w = threadIdx.x; w < 1024; w += 256) {
        const int kt = w >> 5, lane = w & 31;
        const int g = lane >> 2, t = lane & 3;
        const int kc = kt * 16 + 2 * t;
        uint32_t r0 = *reinterpret_cast<const uint32_t*>(&sh[g][kc]);
        uint32_t r1 = *reinterpret_cast<const uint32_t*>(&sh[g + 8][kc]);
        uint32_t r2 = *reinterpret_cast<const uint32_t*>(&sh[g][kc + 8]);
        uint32_t r3 = *reinterpret_cast<const uint32_t*>(&sh[g + 8][kc + 8]);
        int4* dst = reinterpret_cast<int4*>(
            reinterpret_cast<char*>(g_af)
            + (((size_t)rt * 256 + (k0 >> 4) + kt) << 9) + lane * 16);
        *dst = make_int4(r0, r1, r2, r3);
    }
}

// ---------------- W pack: int32 -> f16 fragment-major ----------------
__global__ void __launch_bounds__(256) pack_w_kernel(const int* __restrict__ w) {
    const int nt = blockIdx.y;
    const int k0 = blockIdx.x * 512;
    __shared__ __half sh[8][520];

    #pragma unroll
    for (int u = threadIdx.x; u < 1024; u += 256) {
        const int row = u >> 7, c4 = u & 127;
        int4 v = *reinterpret_cast<const int4*>(
            w + (size_t)(nt * 8 + row) * KDIM + k0 + c4 * 4);
        __half2* d = reinterpret_cast<__half2*>(&sh[row][c4 * 4]);
        d[0] = __floats2half2_rn((float)v.x, (float)v.y);
        d[1] = __floats2half2_rn((float)v.z, (float)v.w);
    }
    __syncthreads();

    #pragma unroll
    for (int u2 = threadIdx.x; u2 < 1024; u2 += 256) {
        const int kt = u2 >> 5, lane = u2 & 31;
        const int g = lane >> 2, t = lane & 3;
        const int kc = kt * 16 + 2 * t;
        uint32_t b0 = *reinterpret_cast<const uint32_t*>(&sh[g][kc]);
        uint32_t b1 = *reinterpret_cast<const uint32_t*>(&sh[g][kc + 8]);
        int2* dst = reinterpret_cast<int2*>(
            reinterpret_cast<char*>(g_wf)
            + (((size_t)nt * 256 + (k0 >> 4) + kt) << 8) + lane * 8);
        *dst = make_int2(b0, b1);
    }
}

// ---------------- main GEMM ----------------
__global__ void __launch_bounds__(256, 2) gemm_kernel(
    const float* __restrict__ scales, float* __restrict__ out)
{
    extern __shared__ char smem[];
    const uint32_t sbase = smem_u32(smem);

    const int tid  = threadIdx.x;
    const int lane = tid & 31;
    const int wid  = tid >> 5;        // 0..7
    const int wm   = wid >> 2;        // 0..1 (64-row slab)
    const int wn   = wid & 3;         // 0..3 (32-col slab)
    const int g    = lane >> 2;
    const int t    = lane & 3;

    // grouped-M raster: 8 m-tiles per group across 32 n-tiles
    const int num_n  = NDIM / BN;     // 32
    const int GROUPM = 8;
    const int bid = blockIdx.x;
    const int grp = bid / (GROUPM * num_n);
    const int rem = bid % (GROUPM * num_n);
    const int m0 = (grp * GROUPM + (rem % GROUPM)) * BM;
    const int n0 = (rem / GROUPM) * BN;
    const int rt0 = m0 >> 4;
    const int nt0 = n0 >> 3;

    float acc[4][4][4];
    #pragma unroll
    for (int i = 0; i < 4; i++)
        #pragma unroll
        for (int j = 0; j < 4; j++)
            #pragma unroll
            for (int c = 0; c < 4; c++) acc[i][j][c] = 0.0f;

    const char* gA = reinterpret_cast<const char*>(g_af);
    const char* gB = reinterpret_cast<const char*>(g_wf);

    // A stage layout: [mi(8)][ks(4)][512B] ; B: [nj(16)][ks(4)][256B]
    #define ISSUE_STAGE(kt_, slot_)                                            \
    do {                                                                       \
        const int _kt4 = (kt_) * 4;                                            \
        const uint32_t _sa = sbase + (uint32_t)(slot_) * STAGE_BYTES;          \
        const uint32_t _sb = _sa + A_ST_BYTES;                                 \
        _Pragma("unroll")                                                      \
        for (int u = tid; u < 1024; u += 256) {        /* A: 16KB */           \
            const int mi = u >> 7;                                             \
            cp_async16(_sa + (u << 4),                                         \
                gA + (((size_t)(rt0 + mi) * 256 + _kt4) << 9)                  \
                   + ((u & 127) << 4));                                        \
        }                                                                      \
        _Pragma("unroll")                                                      \
        for (int u = tid; u < 1024; u += 256) {        /* B: 16KB */           \
            const int nj = u >> 6;                                             \
            cp_async16(_sb + (u << 4),                                         \
                gB + (((size_t)(nt0 + nj) * 256 + _kt4) << 8)                  \
                   + ((u & 63) << 4));                                         \
        }                                                                      \
    } while (0)

    ISSUE_STAGE(0, 0); CP_COMMIT();
    ISSUE_STAGE(1, 1); CP_COMMIT();

    int s_cur = 0, s_nxt = 2;
    const uint32_t lane16 = (uint32_t)lane * 16;
    const uint32_t lane8  = (uint32_t)lane * 8;

    for (int kt = 0; kt < NKT; kt++) {
        CP_WAIT(1);
        __syncthreads();

        const int kn = kt + 2;
        if (kn < NKT) ISSUE_STAGE(kn, s_nxt);
        CP_COMMIT();

        const uint32_t sa = sbase + (uint32_t)s_cur * STAGE_BYTES;
        const uint32_t sb = sa + A_ST_BYTES;

        #pragma unroll
        for (int ks = 0; ks < 4; ks++) {
            uint32_t bf[4][2];
            #pragma unroll
            for (int j = 0; j < 4; j++) {
                const uint32_t addr =
                    sb + (uint32_t)(((wn * 4 + j) * 4 + ks) * 256) + lane8;
                asm volatile("ld.shared.v2.u32 {%0,%1}, [%2];"
                             : "=r"(bf[j][0]), "=r"(bf[j][1]) : "r"(addr));
            }
            #pragma unroll
            for (int i = 0; i < 4; i++) {
                uint32_t a0, a1, a2, a3;
                const uint32_t addr =
                    sa + (uint32_t)(((wm * 4 + i) * 4 + ks) * 512) + lane16;
                asm volatile("ld.shared.v4.u32 {%0,%1,%2,%3}, [%4];"
                             : "=r"(a0), "=r"(a1), "=r"(a2), "=r"(a3) : "r"(addr));
                #pragma unroll
                for (int j = 0; j < 4; j++)
                    MMA_F16(acc[i][j], a0, a1, a2, a3, bf[j][0], bf[j][1]);
            }
        }

        s_cur = (s_cur == 2) ? 0 : s_cur + 1;
        s_nxt = (s_nxt == 2) ? 0 : s_nxt + 1;
    }

    // ---- epilogue: scale and store ----
    const int orow0 = m0 + wm * 64;
    const int ocol0 = n0 + wn * 32;
    #pragma unroll
    for (int j = 0; j < 4; j++) {
        const int col = ocol0 + j * 8 + 2 * t;
        const float2 sc = *reinterpret_cast<const float2*>(scales + col);
        #pragma unroll
        for (int i = 0; i < 4; i++) {
            const int row = orow0 + i * 16 + g;
            float2 v0 = { acc[i][j][0] * sc.x, acc[i][j][1] * sc.y };
            float2 v1 = { acc[i][j][2] * sc.x, acc[i][j][3] * sc.y };
            *reinterpret_cast<float2*>(out + (size_t)row * NDIM + col)       = v0;
            *reinterpret_cast<float2*>(out + (size_t)(row + 8) * NDIM + col) = v1;
        }
    }
}

// ---------------- host ----------------
extern "C" void kernel_launch(void* const* d_in, const int* in_sizes, int n_in,
                              void* d_out, int out_size) {
    const float* input  = (const float*)d_in[0];
    const int*   weight = (const int*)d_in[1];
    const float* scales = (const float*)d_in[2];
    float* out = (float*)d_out;

    {
        dim3 ga(KDIM / 512, MDIM / 16);   // (8, 512)
        pack_a_kernel<<<ga, 256>>>(input);
        dim3 gw(KDIM / 512, NDIM / 8);    // (8, 512)
        pack_w_kernel<<<gw, 256>>>(weight);
    }

    cudaFuncSetAttribute(gemm_kernel,
                         cudaFuncAttributeMaxDynamicSharedMemorySize, SMEM_BYTES);
    const int grid = (MDIM / BM) * (NDIM / BN);   // 2048
    gemm_kernel<<<grid, 256, SMEM_BYTES>>>(scales, out);
}